// round 14
// baseline (speedup 1.0000x reference)
#include <cuda_runtime.h>
#include <stdint.h>

#define N_POINTS 1200000
#define NFEAT 5
#define GXD 400
#define GYD 400
#define NCELLS (GXD*GYD)          // 160000
#define NCELLS_PAD 163840         // 40 * 4096
#define MAXV 60000
#define MAXP 32
#define OUT_COORD_OFF (MAXV*MAXP*NFEAT)        // 9,600,000
#define OUT_NUM_OFF   (OUT_COORD_OFF + MAXV*3) // 9,780,000
#define SCAN_BLOCKS 40
#define CELLS_PER_BLOCK 4096       // 1024 threads * 4 cells
#define DYN_TOTAL (NCELLS_PAD + SCAN_BLOCKS)
#define PPT 4

// [0,NCELLS_PAD) = per-cell list heads (0xFFFFFFFF = empty),
// [NCELLS_PAD, DYN_TOTAL) = lookback state. Re-initialized by memsets each launch.
__device__ unsigned g_dyn[DYN_TOTAL];
__device__ int      g_totvox;
__device__ uint2    g_voxlist[MAXV];           // {cell, head}
// rec[perm(idx)] = {x,y,z,prev_bits},{f3,f4,-,-}: written COALESCED in assign
__device__ float4   g_rec[(size_t)N_POINTS * 2];

// bijective permutation making per-thread (4 consecutive points) rec stores coalesced:
// idx = 128a + 4b + c  ->  pos = 128a + 32c + b
__device__ __forceinline__ unsigned rpos(unsigned idx) {
    return ((idx >> 7) << 7) | ((idx & 3u) << 5) | ((idx >> 2) & 31u);
}

__device__ __forceinline__ void do_point(int idx, unsigned pos,
                                         float x, float y, float z,
                                         float f3, float f4) {
    // exact: (v+50)*4 == (v-(-50))/0.25 ; (v+5)*0.125 == (v-(-5))/8
    int cx = (int)floorf((x + 50.0f) * 4.0f);
    int cy = (int)floorf((y + 50.0f) * 4.0f);
    int cz = (int)floorf((z + 5.0f) * 0.125f);
    if (cx >= 0 && cx < GXD && cy >= 0 && cy < GYD && cz == 0) {
        int cell = cy * GXD + cx;
        unsigned prev = atomicExch(&g_dyn[cell], (unsigned)idx);  // ONE scattered op/point
        g_rec[(size_t)pos * 2]     = make_float4(x, y, z, __uint_as_float(prev));
        g_rec[(size_t)pos * 2 + 1] = make_float4(f3, f4, 0.0f, 0.0f);
    }
}

// ---------------- assign: linked-list push, coalesced payload ----------------
__global__ void __launch_bounds__(256) k_assign(const float4* __restrict__ pts4) {
    int t = blockIdx.x * blockDim.x + threadIdx.x;
    if (t >= N_POINTS / PPT) return;
    const float4* src = pts4 + (size_t)t * 5;   // 5 aligned LDG.128, independent
    float4 q0 = src[0], q1 = src[1], q2 = src[2], q3 = src[3], q4 = src[4];
    int base = t * PPT;
    unsigned wb = (((unsigned)t >> 5) << 7) | ((unsigned)t & 31u);  // warpbase + lane
    // point k = floats [5k,5k+5); rec pos = wb + 32k (coalesced across warp per k)
    do_point(base + 0, wb,      q0.x, q0.y, q0.z, q0.w, q1.x);
    do_point(base + 1, wb + 32, q1.y, q1.z, q1.w, q2.x, q2.y);
    do_point(base + 2, wb + 64, q2.z, q2.w, q3.x, q3.y, q3.z);
    do_point(base + 3, wb + 96, q3.w, q4.x, q4.y, q4.z, q4.w);
}

// ---------------- scan: single-wave decoupled lookback + voxel-list compaction ----------------
__global__ void __launch_bounds__(1024, 1) k_scan() {
    __shared__ int wsum[32];
    __shared__ unsigned s_prefix;
    unsigned* state = g_dyn + NCELLS_PAD;
    const int t = threadIdx.x, b = blockIdx.x;
    const int lane = t & 31, w = t >> 5;
    const int c0 = b * CELLS_PER_BLOCK + t * 4;

    uint4 c4 = *(const uint4*)&g_dyn[c0];
    int o0 = (c4.x != 0xFFFFFFFFu) ? 1 : 0;
    int o1 = (c4.y != 0xFFFFFFFFu) ? 1 : 0;
    int o2 = (c4.z != 0xFFFFFFFFu) ? 1 : 0;
    int o3 = (c4.w != 0xFFFFFFFFu) ? 1 : 0;
    int s = o0 + o1 + o2 + o3;

    int x = s;
    #pragma unroll
    for (int o = 1; o < 32; o <<= 1) {
        int v = __shfl_up_sync(0xffffffffu, x, o);
        if (lane >= o) x += v;
    }
    if (lane == 31) wsum[w] = x;
    __syncthreads();
    if (w == 0) {
        int y = wsum[lane];
        #pragma unroll
        for (int o = 1; o < 32; o <<= 1) {
            int v = __shfl_up_sync(0xffffffffu, y, o);
            if (lane >= o) y += v;
        }
        wsum[lane] = y;
    }
    __syncthreads();
    int incl = x + (w ? wsum[w - 1] : 0);
    unsigned agg = (unsigned)wsum[31];

    if (t == 0) {
        if (b == 0) atomicExch(&state[0], (2u << 30) | agg);
        else        atomicExch(&state[b], (1u << 30) | agg);
    }
    if (w == 0) {
        if (b == 0) { if (lane == 0) s_prefix = 0; }
        else {
            unsigned run = 0;
            int j = b - 1 - lane;
            for (;;) {
                unsigned sv = (j >= 0) ? *(volatile unsigned*)&state[j] : (2u << 30);
                unsigned flag = sv >> 30;
                if (__all_sync(0xffffffffu, flag != 0u)) {
                    unsigned pm = __ballot_sync(0xffffffffu, flag >= 2u);
                    int fp = (pm != 0u) ? (__ffs(pm) - 1) : -1;
                    unsigned contrib = (fp < 0 || lane <= fp) ? (sv & 0x3FFFFFFFu) : 0u;
                    #pragma unroll
                    for (int o = 16; o; o >>= 1)
                        contrib += __shfl_down_sync(0xffffffffu, contrib, o);
                    contrib = __shfl_sync(0xffffffffu, contrib, 0);
                    run += contrib;
                    if (fp >= 0) break;
                    j -= 32;
                }
            }
            if (lane == 0) {
                s_prefix = run;
                atomicExch(&state[b], (2u << 30) | (run + agg));
            }
        }
    }
    __syncthreads();

    int e = (int)s_prefix + incl - s;
    if (o0) { if (e < MAXV) g_voxlist[e] = make_uint2((unsigned)(c0+0), c4.x); e++; }
    if (o1) { if (e < MAXV) g_voxlist[e] = make_uint2((unsigned)(c0+1), c4.y); e++; }
    if (o2) { if (e < MAXV) g_voxlist[e] = make_uint2((unsigned)(c0+2), c4.z); e++; }
    if (o3) { if (e < MAXV) g_voxlist[e] = make_uint2((unsigned)(c0+3), c4.w); e++; }
    if (b == SCAN_BLOCKS - 1 && t == 1023) g_totvox = e;
}

// ---------------- emit: list walk + rec gather + rank + coalesced write ----------------
__global__ void __launch_bounds__(256) k_emit(const float* __restrict__ pts,
                                              float* __restrict__ out) {
    int gid  = blockIdx.x * blockDim.x + threadIdx.x;
    int gw   = gid >> 5;                  // voxel index
    int lane = threadIdx.x & 31;
    int w    = (threadIdx.x >> 5) & 7;
    __shared__ float    sbuf[8][160];
    __shared__ unsigned sidx[8][32];

    if (gw >= MAXV) return;
    int tv = g_totvox;
    if (gw >= tv) {
        float4 z = make_float4(0.f, 0.f, 0.f, 0.f);
        float4* dst = (float4*)(out + (size_t)gw * (MAXP * NFEAT));
        for (int j = lane; j < 40; j += 32) __stcs(&dst[j], z);
        if (lane == 0) {
            float* oc = out + OUT_COORD_OFF + (size_t)gw * 3;
            __stcs(&oc[0], 0.f); __stcs(&oc[1], 0.f); __stcs(&oc[2], 0.f);
            __stcs(&out[OUT_NUM_OFF + gw], 0.f);
        }
        return;
    }

    uint2 ve = __ldcs(&g_voxlist[gw]);
    int cell = (int)ve.x;
    float f0 = 0.f, f1 = 0.f, f2 = 0.f, f3 = 0.f, f4 = 0.f;
    int slot, n, m = 0;

    // lane 0 walks the list (avg ~5 hops), collecting point indices
    if (lane == 0) {
        unsigned h = ve.y;
        while (h != 0xFFFFFFFFu && m < 33) {
            if (m < 32) sidx[w][m] = h;
            m++;
            const float* pr = (const float*)&g_rec[(size_t)rpos(h) * 2];
            h = __float_as_uint(__ldg(pr + 3));
        }
    }
    __syncwarp();
    m = __shfl_sync(0xffffffffu, m, 0);

    if (m <= MAXP) {
        n = m;
        unsigned idx = 0x7fffffffu;
        if (lane < m) {
            idx = sidx[w][lane];
            size_t p = (size_t)rpos(idx) * 2;
            float4 a  = g_rec[p];       // 32B rec: both loads same 128B line
            float4 bb = g_rec[p + 1];
            f0 = a.x; f1 = a.y; f2 = a.z; f3 = bb.x; f4 = bb.y;
        }
        int iv = (int)idx, rank = 0;
        #pragma unroll
        for (int k = 0; k < 32; k++) {
            int o = __shfl_sync(0xffffffffu, iv, k);
            rank += (o < iv) ? 1 : 0;
        }
        slot = (lane < m) ? rank : lane;   // ranks tile [0,m), idle lanes tile [m,32)
    } else {
        // overflow fallback (statistically never): first 32 matches scanning ascending j
        // are exactly the 32 smallest original indices, already in order.
        n = MAXP;
        slot = lane;
        if (lane == 0) {
            int cnt2 = 0;
            for (int j = 0; j < N_POINTS && cnt2 < MAXP; j++) {
                const float* p = pts + (size_t)j * NFEAT;
                int cx = (int)floorf((p[0] + 50.0f) * 4.0f);
                int cy = (int)floorf((p[1] + 50.0f) * 4.0f);
                int cz = (int)floorf((p[2] + 5.0f) * 0.125f);
                if (cx >= 0 && cx < GXD && cy >= 0 && cy < GYD && cz == 0 &&
                    cy * GXD + cx == cell) sidx[w][cnt2++] = (unsigned)j;
            }
        }
        __syncwarp();
        unsigned idx = sidx[w][lane];
        const float* p = pts + (size_t)idx * NFEAT;
        f0 = p[0]; f1 = p[1]; f2 = p[2]; f3 = p[3]; f4 = p[4];
    }

    // stage ranked points in smem (stride 5 coprime to 32 -> conflict-free),
    // then write the 640B voxel row coalesced with streaming stores.
    float* sb = sbuf[w];
    float* d = sb + slot * NFEAT;
    d[0] = f0; d[1] = f1; d[2] = f2; d[3] = f3; d[4] = f4;
    __syncwarp();
    float4* s4 = (float4*)sb;
    float4* dst = (float4*)(out + (size_t)gw * (MAXP * NFEAT));
    #pragma unroll
    for (int j = lane; j < 40; j += 32) __stcs(&dst[j], s4[j]);
    if (lane == 0) {
        int cy = cell / GXD, cx = cell - cy * GXD;
        float* oc = out + OUT_COORD_OFF + (size_t)gw * 3;
        __stcs(&oc[0], 0.0f);           // z
        __stcs(&oc[1], (float)cy);      // y
        __stcs(&oc[2], (float)cx);      // x
        __stcs(&out[OUT_NUM_OFF + gw], (float)n);
    }
}

extern "C" void kernel_launch(void* const* d_in, const int* in_sizes, int n_in,
                              void* d_out, int out_size) {
    const float* pts = (const float*)d_in[0];
    float* out = (float*)d_out;
    (void)in_sizes; (void)n_in; (void)out_size;

    void* dynptr = nullptr;
    cudaGetSymbolAddress(&dynptr, g_dyn);
    // heads = 0xFFFFFFFF (empty lists), lookback state = 0
    cudaMemsetAsync(dynptr, 0xFF, sizeof(unsigned) * NCELLS_PAD, 0);
    cudaMemsetAsync((char*)dynptr + sizeof(unsigned) * NCELLS_PAD, 0,
                    sizeof(unsigned) * SCAN_BLOCKS, 0);

    k_assign<<<(N_POINTS / PPT + 255) / 256, 256>>>((const float4*)pts);
    k_scan  <<<SCAN_BLOCKS, 1024>>>();
    k_emit  <<<(MAXV * 32) / 256, 256>>>(pts, out);
}

// round 15
// speedup vs baseline: 1.4916x; 1.4916x over previous
#include <cuda_runtime.h>
#include <stdint.h>

#define N_POINTS 1200000
#define NFEAT 5
#define GXD 400
#define GYD 400
#define NCELLS (GXD*GYD)          // 160000
#define NCELLS_PAD 163840         // 40 * 4096
#define MAXV 60000
#define MAXP 32
#define OUT_COORD_OFF (MAXV*MAXP*NFEAT)        // 9,600,000
#define OUT_NUM_OFF   (OUT_COORD_OFF + MAXV*3) // 9,780,000
#define SCAN_BLOCKS 40
#define CELLS_PER_BLOCK 4096       // 1024 threads * 4 cells
#define DYN_TOTAL (NCELLS_PAD + SCAN_BLOCKS)
#define PPT 4                      // points per thread in assign

// [0,NCELLS_PAD) = per-cell counts, then SCAN_BLOCKS lookback states.
// Zero-initialized at load; k_emit re-zeroes it each launch for the next replay.
__device__ unsigned g_dyn[DYN_TOTAL];
__device__ int      g_totvox;
__device__ unsigned g_voxlist[MAXV];            // cell(18b) | min(cnt,16383)<<18
// slotA[cell][rank] = {x,y,z,idx_bits}: 16B scattered store (one sector per point) —
// emit only needs to gather f3,f4 from pts.
__device__ float4   g_slotA[(size_t)NCELLS * MAXP];

__device__ __forceinline__ void do_point(int idx, float x, float y, float z) {
    // exact: (v+50)*4 == (v-(-50))/0.25 ; (v+5)*0.125 == (v-(-5))/8
    int cx = (int)floorf((x + 50.0f) * 4.0f);
    int cy = (int)floorf((y + 50.0f) * 4.0f);
    int cz = (int)floorf((z + 5.0f) * 0.125f);
    if (cx >= 0 && cx < GXD && cy >= 0 && cy < GYD && cz == 0) {
        int cell = cy * GXD + cx;
        unsigned r = atomicAdd(&g_dyn[cell], 1u);
        if (r < MAXP)
            g_slotA[(size_t)cell * MAXP + r] = make_float4(x, y, z, __int_as_float(idx));
    }
}

// ---------------- assign: 4 points/thread (atomic-throughput bound, ~18us floor) ----------------
__global__ void __launch_bounds__(256) k_assign(const float4* __restrict__ pts4) {
    int t = blockIdx.x * blockDim.x + threadIdx.x;
    if (t >= N_POINTS / PPT) return;
    // 4 points = 80 bytes = 5 aligned float4 loads, all independent
    const float4* src = pts4 + (size_t)t * 5;
    float4 q0 = src[0], q1 = src[1], q2 = src[2], q3 = src[3], q4 = src[4];
    int base = t * PPT;
    // point k = floats [5k,5k+5) across q0..q4; only xyz needed here
    do_point(base + 0, q0.x, q0.y, q0.z);
    do_point(base + 1, q1.y, q1.z, q1.w);
    do_point(base + 2, q2.z, q2.w, q3.x);
    do_point(base + 3, q3.w, q4.x, q4.y);
}

// ---------------- scan: single-wave decoupled lookback + voxel-list compaction ----------------
__global__ void __launch_bounds__(1024, 1) k_scan() {
    __shared__ int wsum[32];
    __shared__ unsigned s_prefix;
    unsigned* state = g_dyn + NCELLS_PAD;
    const int t = threadIdx.x, b = blockIdx.x;
    const int lane = t & 31, w = t >> 5;
    const int c0 = b * CELLS_PER_BLOCK + t * 4;

    uint4 c4 = *(const uint4*)&g_dyn[c0];
    int o0 = c4.x ? 1 : 0, o1 = c4.y ? 1 : 0, o2 = c4.z ? 1 : 0, o3 = c4.w ? 1 : 0;
    int s = o0 + o1 + o2 + o3;

    int x = s;
    #pragma unroll
    for (int o = 1; o < 32; o <<= 1) {
        int v = __shfl_up_sync(0xffffffffu, x, o);
        if (lane >= o) x += v;
    }
    if (lane == 31) wsum[w] = x;
    __syncthreads();
    if (w == 0) {
        int y = wsum[lane];
        #pragma unroll
        for (int o = 1; o < 32; o <<= 1) {
            int v = __shfl_up_sync(0xffffffffu, y, o);
            if (lane >= o) y += v;
        }
        wsum[lane] = y;
    }
    __syncthreads();
    int incl = x + (w ? wsum[w - 1] : 0);
    unsigned agg = (unsigned)wsum[31];

    if (t == 0) {
        if (b == 0) atomicExch(&state[0], (2u << 30) | agg);
        else        atomicExch(&state[b], (1u << 30) | agg);
    }
    if (w == 0) {
        if (b == 0) { if (lane == 0) s_prefix = 0; }
        else {
            unsigned run = 0;
            int j = b - 1 - lane;
            for (;;) {
                unsigned sv = (j >= 0) ? *(volatile unsigned*)&state[j] : (2u << 30);
                unsigned flag = sv >> 30;
                if (__all_sync(0xffffffffu, flag != 0u)) {
                    unsigned pm = __ballot_sync(0xffffffffu, flag >= 2u);
                    int fp = (pm != 0u) ? (__ffs(pm) - 1) : -1;
                    unsigned contrib = (fp < 0 || lane <= fp) ? (sv & 0x3FFFFFFFu) : 0u;
                    #pragma unroll
                    for (int o = 16; o; o >>= 1)
                        contrib += __shfl_down_sync(0xffffffffu, contrib, o);
                    contrib = __shfl_sync(0xffffffffu, contrib, 0);
                    run += contrib;
                    if (fp >= 0) break;
                    j -= 32;
                }
            }
            if (lane == 0) {
                s_prefix = run;
                atomicExch(&state[b], (2u << 30) | (run + agg));
            }
        }
    }
    __syncthreads();

    int e = (int)s_prefix + incl - s;   // exclusive prefix of occupancy before cell c0
    if (o0) { if (e < MAXV) g_voxlist[e] = (unsigned)(c0+0) | (umin(c4.x, 16383u) << 18); e++; }
    if (o1) { if (e < MAXV) g_voxlist[e] = (unsigned)(c0+1) | (umin(c4.y, 16383u) << 18); e++; }
    if (o2) { if (e < MAXV) g_voxlist[e] = (unsigned)(c0+2) | (umin(c4.z, 16383u) << 18); e++; }
    if (o3) { if (e < MAXV) g_voxlist[e] = (unsigned)(c0+3) | (umin(c4.w, 16383u) << 18); e++; }
    if (b == SCAN_BLOCKS - 1 && t == 1023) g_totvox = e;
}

// ---------------- emit: dynamic-length rank loop (cnt avg ~4, not 32) ----------------
__global__ void __launch_bounds__(256) k_emit(const float* __restrict__ pts,
                                              float* __restrict__ out) {
    int gid  = blockIdx.x * blockDim.x + threadIdx.x;
    int gw   = gid >> 5;                  // voxel index
    int lane = threadIdx.x & 31;
    int w    = (threadIdx.x >> 5) & 7;
    __shared__ float sbuf[8][160];
    __shared__ int   sidx[8][32];

    // reset counters + lookback state for the next replay (globals start zeroed at load)
    if (gid < DYN_TOTAL) g_dyn[gid] = 0;

    if (gw >= MAXV) return;
    int tv = g_totvox;
    if (gw >= tv) {
        // zero-fill unowned voxel (no-op when totvox >= MAXV)
        float4 z = make_float4(0.f, 0.f, 0.f, 0.f);
        float4* dst = (float4*)(out + (size_t)gw * (MAXP * NFEAT));
        for (int j = lane; j < 40; j += 32) __stcs(&dst[j], z);
        if (lane == 0) {
            float* oc = out + OUT_COORD_OFF + (size_t)gw * 3;
            __stcs(&oc[0], 0.f); __stcs(&oc[1], 0.f); __stcs(&oc[2], 0.f);
            __stcs(&out[OUT_NUM_OFF + gw], 0.f);
        }
        return;
    }

    unsigned packed = __ldcs(&g_voxlist[gw]);
    int cell = (int)(packed & 0x3FFFFu);
    int cnt  = (int)(packed >> 18);
    float f0 = 0.f, f1 = 0.f, f2 = 0.f, f3 = 0.f, f4 = 0.f;
    int slot, n;

    if (cnt <= MAXP) {
        n = cnt;
        int idx = 0x7fffffff;
        if (lane < cnt) {
            // coalesced: active lanes read contiguous 16B/lane
            float4 a = __ldcs(&g_slotA[(size_t)cell * MAXP + lane]);
            idx = __float_as_int(a.w);
            f0 = a.x; f1 = a.y; f2 = a.z;
            // f3,f4 live at floats 5i+3, 5i+4. One aligned 16B word starting at
            // (5i+3)>>2 holds both unless (i+3)&3 == 3 (25%: f4 = next word's .x).
            const float4* p4 = (const float4*)pts;
            int w1 = (5 * idx + 3) >> 2;
            int o  = (idx + 3) & 3;
            float4 A = __ldg(&p4[w1]);
            f3 = o==0 ? A.x : o==1 ? A.y : o==2 ? A.z : A.w;
            if (o == 3) f4 = __ldg((const float*)&p4[w1 + 1]);
            else        f4 = o==0 ? A.y : o==1 ? A.z : A.w;
        }
        // dynamic-length rank: only cnt comparisons (avg ~4), not 32
        int rank = 0;
        for (int k = 0; k < cnt; k++) {
            int o = __shfl_sync(0xffffffffu, idx, k);
            rank += (o < idx) ? 1 : 0;
        }
        slot = (lane < cnt) ? rank : lane;   // ranks tile [0,cnt), idle lanes tile [cnt,32)
    } else {
        // overflow fallback (statistically never): first 32 matches scanning ascending j
        // are exactly the 32 smallest original indices, already in order.
        n = MAXP;
        slot = lane;
        if (lane == 0) {
            int m = 0;
            for (int j = 0; j < N_POINTS && m < MAXP; j++) {
                const float* p = pts + (size_t)j * NFEAT;
                int cx = (int)floorf((p[0] + 50.0f) * 4.0f);
                int cy = (int)floorf((p[1] + 50.0f) * 4.0f);
                int cz = (int)floorf((p[2] + 5.0f) * 0.125f);
                if (cx >= 0 && cx < GXD && cy >= 0 && cy < GYD && cz == 0 &&
                    cy * GXD + cx == cell) sidx[w][m++] = j;
            }
        }
        __syncwarp();
        int idx = sidx[w][lane];
        const float* p = pts + (size_t)idx * NFEAT;
        f0 = p[0]; f1 = p[1]; f2 = p[2]; f3 = p[3]; f4 = p[4];
    }

    // stage ranked points in smem (stride 5 coprime to 32 -> conflict-free),
    // then write the 640B voxel row coalesced with streaming stores.
    float* sb = sbuf[w];
    float* d = sb + slot * NFEAT;
    d[0] = f0; d[1] = f1; d[2] = f2; d[3] = f3; d[4] = f4;
    __syncwarp();
    float4* s4 = (float4*)sb;
    float4* dst = (float4*)(out + (size_t)gw * (MAXP * NFEAT));
    #pragma unroll
    for (int j = lane; j < 40; j += 32) __stcs(&dst[j], s4[j]);
    if (lane == 0) {
        int cy = cell / GXD, cx = cell - cy * GXD;
        float* oc = out + OUT_COORD_OFF + (size_t)gw * 3;
        __stcs(&oc[0], 0.0f);           // z
        __stcs(&oc[1], (float)cy);      // y
        __stcs(&oc[2], (float)cx);      // x
        __stcs(&out[OUT_NUM_OFF + gw], (float)n);
    }
}

extern "C" void kernel_launch(void* const* d_in, const int* in_sizes, int n_in,
                              void* d_out, int out_size) {
    const float* pts = (const float*)d_in[0];
    float* out = (float*)d_out;
    (void)in_sizes; (void)n_in; (void)out_size;

    k_assign<<<(N_POINTS / PPT + 255) / 256, 256>>>((const float4*)pts);
    k_scan  <<<SCAN_BLOCKS, 1024>>>();
    k_emit  <<<(MAXV * 32) / 256, 256>>>(pts, out);
}

// round 16
// speedup vs baseline: 1.5331x; 1.0279x over previous
#include <cuda_runtime.h>
#include <stdint.h>

#define N_POINTS 1200000
#define NFEAT 5
#define GXD 400
#define GYD 400
#define NCELLS (GXD*GYD)          // 160000
#define NCELLS_PAD 163840         // 40 * 4096
#define MAXV 60000
#define MAXP 32
#define OUT_COORD_OFF (MAXV*MAXP*NFEAT)        // 9,600,000
#define OUT_NUM_OFF   (OUT_COORD_OFF + MAXV*3) // 9,780,000
#define SCAN_BLOCKS 40
#define CELLS_PER_BLOCK 4096       // 1024 threads * 4 cells
#define DYN_TOTAL (NCELLS_PAD + SCAN_BLOCKS)
#define PPT 4                      // points per thread in assign

// [0,NCELLS_PAD) = per-cell counts, then SCAN_BLOCKS lookback states.
// Zero-initialized at load; k_emit re-zeroes it each launch for the next replay.
__device__ unsigned g_dyn[DYN_TOTAL];
__device__ int      g_totvox;
__device__ unsigned g_voxlist[MAXV];            // cell(18b) | min(cnt,16383)<<18
// slotA[cell][rank] = {x,y,z,idx_bits}: 16B scattered store (one sector per point) —
// emit only needs to gather f3,f4 from pts.
__device__ float4   g_slotA[(size_t)NCELLS * MAXP];

__device__ __forceinline__ void do_point(int idx, float x, float y, float z) {
    // exact: (v+50)*4 == (v-(-50))/0.25 ; (v+5)*0.125 == (v-(-5))/8
    int cx = (int)floorf((x + 50.0f) * 4.0f);
    int cy = (int)floorf((y + 50.0f) * 4.0f);
    int cz = (int)floorf((z + 5.0f) * 0.125f);
    if (cx >= 0 && cx < GXD && cy >= 0 && cy < GYD && cz == 0) {
        int cell = cy * GXD + cx;
        unsigned r = atomicAdd(&g_dyn[cell], 1u);
        if (r < MAXP)
            g_slotA[(size_t)cell * MAXP + r] = make_float4(x, y, z, __int_as_float(idx));
    }
}

// ---------------- assign: 4 points/thread (atomic-throughput bound, ~18us floor) ----------------
__global__ void __launch_bounds__(256) k_assign(const float4* __restrict__ pts4) {
    int t = blockIdx.x * blockDim.x + threadIdx.x;
    if (t >= N_POINTS / PPT) return;
    const float4* src = pts4 + (size_t)t * 5;   // 5 aligned LDG.128, independent
    float4 q0 = src[0], q1 = src[1], q2 = src[2], q3 = src[3], q4 = src[4];
    int base = t * PPT;
    do_point(base + 0, q0.x, q0.y, q0.z);
    do_point(base + 1, q1.y, q1.z, q1.w);
    do_point(base + 2, q2.z, q2.w, q3.x);
    do_point(base + 3, q3.w, q4.x, q4.y);
}

// ---------------- scan: single-wave decoupled lookback + voxel-list compaction ----------------
__global__ void __launch_bounds__(1024, 1) k_scan() {
    __shared__ int wsum[32];
    __shared__ unsigned s_prefix;
    unsigned* state = g_dyn + NCELLS_PAD;
    const int t = threadIdx.x, b = blockIdx.x;
    const int lane = t & 31, w = t >> 5;
    const int c0 = b * CELLS_PER_BLOCK + t * 4;

    uint4 c4 = *(const uint4*)&g_dyn[c0];
    int o0 = c4.x ? 1 : 0, o1 = c4.y ? 1 : 0, o2 = c4.z ? 1 : 0, o3 = c4.w ? 1 : 0;
    int s = o0 + o1 + o2 + o3;

    int x = s;
    #pragma unroll
    for (int o = 1; o < 32; o <<= 1) {
        int v = __shfl_up_sync(0xffffffffu, x, o);
        if (lane >= o) x += v;
    }
    if (lane == 31) wsum[w] = x;
    __syncthreads();
    if (w == 0) {
        int y = wsum[lane];
        #pragma unroll
        for (int o = 1; o < 32; o <<= 1) {
            int v = __shfl_up_sync(0xffffffffu, y, o);
            if (lane >= o) y += v;
        }
        wsum[lane] = y;
    }
    __syncthreads();
    int incl = x + (w ? wsum[w - 1] : 0);
    unsigned agg = (unsigned)wsum[31];

    if (t == 0) {
        if (b == 0) atomicExch(&state[0], (2u << 30) | agg);
        else        atomicExch(&state[b], (1u << 30) | agg);
    }
    if (w == 0) {
        if (b == 0) { if (lane == 0) s_prefix = 0; }
        else {
            unsigned run = 0;
            int j = b - 1 - lane;
            for (;;) {
                unsigned sv = (j >= 0) ? *(volatile unsigned*)&state[j] : (2u << 30);
                unsigned flag = sv >> 30;
                if (__all_sync(0xffffffffu, flag != 0u)) {
                    unsigned pm = __ballot_sync(0xffffffffu, flag >= 2u);
                    int fp = (pm != 0u) ? (__ffs(pm) - 1) : -1;
                    unsigned contrib = (fp < 0 || lane <= fp) ? (sv & 0x3FFFFFFFu) : 0u;
                    #pragma unroll
                    for (int o = 16; o; o >>= 1)
                        contrib += __shfl_down_sync(0xffffffffu, contrib, o);
                    contrib = __shfl_sync(0xffffffffu, contrib, 0);
                    run += contrib;
                    if (fp >= 0) break;
                    j -= 32;
                }
            }
            if (lane == 0) {
                s_prefix = run;
                atomicExch(&state[b], (2u << 30) | (run + agg));
            }
        }
    }
    __syncthreads();

    int e = (int)s_prefix + incl - s;
    if (o0) { if (e < MAXV) g_voxlist[e] = (unsigned)(c0+0) | (umin(c4.x, 16383u) << 18); e++; }
    if (o1) { if (e < MAXV) g_voxlist[e] = (unsigned)(c0+1) | (umin(c4.y, 16383u) << 18); e++; }
    if (o2) { if (e < MAXV) g_voxlist[e] = (unsigned)(c0+2) | (umin(c4.z, 16383u) << 18); e++; }
    if (o3) { if (e < MAXV) g_voxlist[e] = (unsigned)(c0+3) | (umin(c4.w, 16383u) << 18); e++; }
    if (b == SCAN_BLOCKS - 1 && t == 1023) g_totvox = e;
}

// gather f3,f4 for point idx: floats 5i+3, 5i+4 (one 16B word unless (i+3)&3==3)
__device__ __forceinline__ void gather_tail(const float4* __restrict__ p4, int idx,
                                            float& f3, float& f4) {
    int w1 = (5 * idx + 3) >> 2;
    int o  = (idx + 3) & 3;
    float4 A = __ldg(&p4[w1]);
    f3 = o==0 ? A.x : o==1 ? A.y : o==2 ? A.z : A.w;
    if (o == 3) f4 = __ldg((const float*)&p4[w1 + 1]);
    else        f4 = o==0 ? A.y : o==1 ? A.z : A.w;
}

// ---------------- emit: one HALF-WARP per voxel ----------------
__global__ void __launch_bounds__(256) k_emit(const float* __restrict__ pts,
                                              float* __restrict__ out) {
    int gid = blockIdx.x * blockDim.x + threadIdx.x;
    int gw  = gid >> 4;                   // voxel index (one per half-warp)
    int hl  = threadIdx.x & 15;           // lane within half
    int rg  = threadIdx.x >> 4;           // staging region 0..15 in block
    unsigned hmask = 0xFFFFu << (threadIdx.x & 16);
    __shared__ float sbuf[16][160];
    __shared__ int   sidx[16][32];

    // reset counters + lookback state for next replay (globals start zeroed at load)
    if (gid < DYN_TOTAL) g_dyn[gid] = 0;

    if (gw >= MAXV) return;
    int tv = g_totvox;
    float4* dst = (float4*)(out + (size_t)gw * (MAXP * NFEAT));
    if (gw >= tv) {
        float4 z = make_float4(0.f, 0.f, 0.f, 0.f);
        for (int j = hl; j < 40; j += 16) __stcs(&dst[j], z);
        if (hl == 0) {
            float* oc = out + OUT_COORD_OFF + (size_t)gw * 3;
            __stcs(&oc[0], 0.f); __stcs(&oc[1], 0.f); __stcs(&oc[2], 0.f);
            __stcs(&out[OUT_NUM_OFF + gw], 0.f);
        }
        return;
    }

    unsigned packed = __ldcs(&g_voxlist[gw]);
    int cell = (int)(packed & 0x3FFFFu);
    int cnt  = (int)(packed >> 18);
    const float4* p4 = (const float4*)pts;

    float a0=0.f,a1=0.f,a2=0.f,a3=0.f,a4=0.f;   // record for slot hl
    float b0=0.f,b1=0.f,b2=0.f,b3=0.f,b4=0.f;   // record for slot hl+16
    int slotA, slotB, n;

    if (cnt <= MAXP) {
        n = cnt;
        int s0 = hl, s1 = hl + 16;
        int idxA = 0x7fffffff, idxB = 0x7fffffff;
        if (s0 < cnt) {
            float4 a = __ldcs(&g_slotA[(size_t)cell * MAXP + s0]);
            idxA = __float_as_int(a.w);
            a0 = a.x; a1 = a.y; a2 = a.z;
            gather_tail(p4, idxA, a3, a4);
        }
        if (s1 < cnt) {
            float4 a = __ldcs(&g_slotA[(size_t)cell * MAXP + s1]);
            idxB = __float_as_int(a.w);
            b0 = a.x; b1 = a.y; b2 = a.z;
            gather_tail(p4, idxB, b3, b4);
        }
        int rankA = 0, rankB = 0;
        int kA = cnt < 16 ? cnt : 16;
        for (int k = 0; k < kA; k++) {
            int o = __shfl_sync(hmask, idxA, k, 16);
            rankA += (o < idxA) ? 1 : 0;
            rankB += (o < idxB) ? 1 : 0;
        }
        if (cnt > 16) {
            int kB = cnt - 16;
            for (int k = 0; k < kB; k++) {
                int o = __shfl_sync(hmask, idxB, k, 16);
                rankA += (o < idxA) ? 1 : 0;
                rankB += (o < idxB) ? 1 : 0;
            }
        }
        slotA = (s0 < cnt) ? rankA : s0;   // active ranks tile [0,cnt), idles tile [cnt,32)
        slotB = (s1 < cnt) ? rankB : s1;
    } else {
        // overflow fallback (statistically never): first 32 matches scanning ascending j
        // are exactly the 32 smallest original indices, already in order.
        n = MAXP;
        slotA = hl; slotB = hl + 16;
        if (hl == 0) {
            int m = 0;
            for (int j = 0; j < N_POINTS && m < MAXP; j++) {
                const float* p = pts + (size_t)j * NFEAT;
                int cx = (int)floorf((p[0] + 50.0f) * 4.0f);
                int cy = (int)floorf((p[1] + 50.0f) * 4.0f);
                int cz = (int)floorf((p[2] + 5.0f) * 0.125f);
                if (cx >= 0 && cx < GXD && cy >= 0 && cy < GYD && cz == 0 &&
                    cy * GXD + cx == cell) sidx[rg][m++] = j;
            }
        }
        __syncwarp(hmask);
        int iA = sidx[rg][hl], iB = sidx[rg][hl + 16];
        const float* pA = pts + (size_t)iA * NFEAT;
        const float* pB = pts + (size_t)iB * NFEAT;
        a0 = pA[0]; a1 = pA[1]; a2 = pA[2]; a3 = pA[3]; a4 = pA[4];
        b0 = pB[0]; b1 = pB[1]; b2 = pB[2]; b3 = pB[3]; b4 = pB[4];
    }

    // stage both records (stride 5 across 32 slots -> conflict-light), write coalesced
    float* sb = sbuf[rg];
    float* dA = sb + slotA * NFEAT;
    dA[0] = a0; dA[1] = a1; dA[2] = a2; dA[3] = a3; dA[4] = a4;
    float* dB = sb + slotB * NFEAT;
    dB[0] = b0; dB[1] = b1; dB[2] = b2; dB[3] = b3; dB[4] = b4;
    __syncwarp(hmask);
    float4* s4 = (float4*)sb;
    #pragma unroll
    for (int j = hl; j < 40; j += 16) __stcs(&dst[j], s4[j]);
    if (hl == 0) {
        int cy = cell / GXD, cx = cell - cy * GXD;
        float* oc = out + OUT_COORD_OFF + (size_t)gw * 3;
        __stcs(&oc[0], 0.0f);           // z
        __stcs(&oc[1], (float)cy);      // y
        __stcs(&oc[2], (float)cx);      // x
        __stcs(&out[OUT_NUM_OFF + gw], (float)n);
    }
}

extern "C" void kernel_launch(void* const* d_in, const int* in_sizes, int n_in,
                              void* d_out, int out_size) {
    const float* pts = (const float*)d_in[0];
    float* out = (float*)d_out;
    (void)in_sizes; (void)n_in; (void)out_size;

    k_assign<<<(N_POINTS / PPT + 255) / 256, 256>>>((const float4*)pts);
    k_scan  <<<SCAN_BLOCKS, 1024>>>();
    k_emit  <<<(MAXV * 16 + 255) / 256, 256>>>(pts, out);
}